// round 4
// baseline (speedup 1.0000x reference)
#include <cuda_runtime.h>
#include <cstdint>

// ---------------------------------------------------------------------------
// MultiMolNet: per-atom typed 3-layer MLP + masked per-molecule sum.
// Identity: sum over all 8 type-MLPs = f_{type}(feats) + (C - Z_type),
// Z_t = f_t(0), C = sum_t Z_t  ->  one MLP eval per atom (8x fewer FLOPs).
// ---------------------------------------------------------------------------

namespace {
constexpr int B_  = 4096;
constexpr int A_  = 64;
constexpr int F_  = 124;
constexpr int T_  = 8;
constexpr int H1_ = 64;
constexpr int H2_ = 16;
constexpr int NATOM = B_ * A_;     // 262144
constexpr int ROW   = F_ + 1;      // 125
constexpr int BM    = 256;         // atoms per MLP tile
constexpr int MLP_BLOCKS = NATOM / BM + T_;   // 1032 >= sum of ceil(cnt_t/BM)

// --- dynamic smem layout for k_mlp (float indices) ---
// Union region U (reused):
//   layer-1 view : w1T[64][126] (8064 fl) then fa[256][34] (8704 fl) = 16768
//   layer-2 view : h1s[256][68] = 17408 fl
constexpr int U_W1T   = 0;           // stride 126 per h row
constexpr int U_FA    = 8064;        // stride 34 per atom row
constexpr int U_H1S   = 0;           // stride 68 per atom row
constexpr int U_SZ    = 17408;
constexpr int S_W2    = U_SZ;            // [64][16] = 1024
constexpr int S_B1    = S_W2 + 1024;     // 64
constexpr int S_B2    = S_B1 + 64;       // 16
constexpr int S_W3    = S_B2 + 16;       // 16
constexpr int S_MISC  = S_W3 + 16;       // [0]=corr, [1]=b3[t]
constexpr int SMEM_FLOATS = S_MISC + 4;
constexpr int SMEM_BYTES  = SMEM_FLOATS * 4;   // ~74 KB
}

// ---- scratch (no allocations allowed) ----
__device__ int   g_counts[T_];
__device__ int   g_bucket[T_ * NATOM];      // 8 MB
__device__ float g_corr[T_];                // C - Z_t
__device__ float g_atom[NATOM];             // per-atom masked contribution

// ---- f32x2 helpers (packed FFMA: PTX-only on sm_103a) ----
__device__ __forceinline__ void ffma2(unsigned long long& d,
                                      unsigned long long a,
                                      unsigned long long b) {
    asm("fma.rn.f32x2 %0, %1, %2, %3;" : "=l"(d) : "l"(a), "l"(b), "l"(d));
}
__device__ __forceinline__ unsigned long long pack2(float lo, float hi) {
    unsigned long long r;
    asm("mov.b64 %0, {%1, %2};" : "=l"(r) : "f"(lo), "f"(hi));
    return r;
}
__device__ __forceinline__ void unpack2(unsigned long long v, float& lo, float& hi) {
    asm("mov.b64 {%0, %1}, %2;" : "=f"(lo), "=f"(hi) : "l"(v));
}

// ===========================================================================
// K0: compute Z_t = f_t(0), corr_t = C - Z_t; zero type counters.
// ===========================================================================
__global__ void k_init(const float* __restrict__ b1, const float* __restrict__ W2,
                       const float* __restrict__ b2, const float* __restrict__ W3,
                       const float* __restrict__ b3) {
    __shared__ float zs[T_];
    int t = threadIdx.x;
    if (t < T_) {
        g_counts[t] = 0;
        float h1z[H1_];
        #pragma unroll
        for (int h = 0; h < H1_; h++) h1z[h] = fmaxf(b1[t * H1_ + h], 0.0f);
        float o = b3[t];
        for (int g = 0; g < H2_; g++) {
            float s = b2[t * H2_ + g];
            #pragma unroll
            for (int k = 0; k < H1_; k++)
                s += h1z[k] * W2[t * H1_ * H2_ + k * H2_ + g];
            o += fmaxf(s, 0.0f) * W3[t * H2_ + g];
        }
        zs[t] = o;
    }
    __syncthreads();
    if (t < T_) {
        float C = 0.0f;
        #pragma unroll
        for (int tt = 0; tt < T_; tt++) C += zs[tt];
        g_corr[t] = C - zs[t];
    }
}

// ===========================================================================
// K1: bucket atom indices by type (block-aggregated atomics).
// Bucket order is nondeterministic but harmless: per-atom values and the
// final reduction are independent of bucket position.
// ===========================================================================
__global__ void k_bucket(const float* __restrict__ x) {
    __shared__ int scnt[T_], sbase[T_];
    int tid = threadIdx.x;
    if (tid < T_) scnt[tid] = 0;
    __syncthreads();
    int i = blockIdx.x * 256 + tid;
    int t = (int)x[(long long)i * ROW];          // type stored in feature 0
    int r = atomicAdd(&scnt[t], 1);
    __syncthreads();
    if (tid < T_) sbase[tid] = atomicAdd(&g_counts[tid], scnt[tid]);
    __syncthreads();
    g_bucket[t * NATOM + sbase[t] + r] = i;
}

// ===========================================================================
// K2: fused 3-layer MLP per (type, 256-atom tile).
//  - W1^T + W2 (+biases) in smem, shared across 256 atoms
//  - layer 1: warp w owns h in [8w,8w+8); lane owns atoms {lane+32j}
//    f32x2 accumulators pair (k, k+1): feats & W1^T pairs are contiguous ->
//    pure LDS.64 + FFMA2, zero pack instructions
//  - layer 2/3 fused per-thread (one atom), f32x2 over output-pairs
// ===========================================================================
__global__ void __launch_bounds__(256, 1)
k_mlp(const float* __restrict__ x,  const float* __restrict__ mask,
      const float* __restrict__ W1, const float* __restrict__ b1,
      const float* __restrict__ W2, const float* __restrict__ b2,
      const float* __restrict__ W3, const float* __restrict__ b3) {
    extern __shared__ float sm[];
    const int tid  = threadIdx.x;
    const int warp = tid >> 5;
    const int lane = tid & 31;

    // ---- map block -> (type, tile) by scanning counts ----
    int t = -1, tile = 0, cnt = 0;
    {
        int rem = blockIdx.x;
        #pragma unroll
        for (int tt = 0; tt < T_; tt++) {
            int c  = g_counts[tt];
            int nt = (c + BM - 1) >> 8;
            if (t < 0) {
                if (rem < nt) { t = tt; tile = rem; cnt = c; }
                else rem -= nt;
            }
        }
    }
    if (t < 0) return;   // uniform exit, before any sync

    // ---- stage per-type parameters ----
    for (int i = tid; i < F_ * H1_; i += 256) {          // W1 -> transposed [h][f]
        int f = i >> 6, h = i & 63;
        sm[U_W1T + h * 126 + f] = W1[t * F_ * H1_ + i];
    }
    for (int i = tid; i < H1_ * H2_; i += 256)
        sm[S_W2 + i] = W2[t * H1_ * H2_ + i];
    if (tid < H1_) sm[S_B1 + tid] = b1[t * H1_ + tid];
    if (tid < H2_) sm[S_B2 + tid] = b2[t * H2_ + tid];
    if (tid < H2_) sm[S_W3 + tid] = W3[t * H2_ + tid];
    if (tid == 0) { sm[S_MISC] = g_corr[t]; sm[S_MISC + 1] = b3[t]; }

    // this thread's atom slot for load phase & layer 2
    const int gi  = tile * BM + tid;
    const int idx = (gi < cnt) ? g_bucket[t * NATOM + gi] : -1;

    // ---- layer 1: K staged in chunks {32,32,32,28} ----
    unsigned long long acc[8][8];
    #pragma unroll
    for (int j = 0; j < 8; j++)
        #pragma unroll
        for (int hh = 0; hh < 8; hh++) acc[j][hh] = 0ULL;

    for (int c = 0; c < 4; c++) {
        const int kb = c * 32;
        const int kl = (c == 3) ? 28 : 32;
        __syncthreads();                       // previous compute done
        {
            float* fr = &sm[U_FA + tid * 34];
            if (idx >= 0) {
                const float* src = x + (long long)idx * ROW + 1 + kb;
                for (int i = 0; i < kl; i++) fr[i] = src[i];   // no OOB reads
                for (int i = kl; i < 32; i++) fr[i] = 0.0f;
            } else {
                #pragma unroll
                for (int i = 0; i < 32; i++) fr[i] = 0.0f;
            }
        }
        __syncthreads();

        // W1^T rows are staged in FULL (stride 126) -> advance by kb.
        // Feature chunks are staged at row slots [0..31] -> NO kb offset.
        const unsigned long long* wq =
            (const unsigned long long*)&sm[U_W1T + warp * 8 * 126 + kb];
        const unsigned long long* fq =
            (const unsigned long long*)&sm[U_FA + lane * 34];
        const int np = kl >> 1;
        #pragma unroll 1
        for (int kp = 0; kp < np; kp++) {
            unsigned long long wp[8], fp[8];
            #pragma unroll
            for (int hh = 0; hh < 8; hh++) wp[hh] = wq[hh * 63];   // row stride 126 fl
            #pragma unroll
            for (int j = 0; j < 8; j++)    fp[j]  = fq[j * 544];   // 32 atoms * 34 fl
            #pragma unroll
            for (int j = 0; j < 8; j++)
                #pragma unroll
                for (int hh = 0; hh < 8; hh++)
                    ffma2(acc[j][hh], fp[j], wp[hh]);
            wq++; fq++;
        }
    }

    // ---- layer-1 epilogue: relu(lo+hi+b1) -> h1s[atom][h] (overlays U) ----
    __syncthreads();                           // all warps done reading U
    {
        float bb[8];
        #pragma unroll
        for (int hh = 0; hh < 8; hh++) bb[hh] = sm[S_B1 + warp * 8 + hh];
        #pragma unroll
        for (int j = 0; j < 8; j++) {
            const int a = j * 32 + lane;
            float v[8];
            #pragma unroll
            for (int hh = 0; hh < 8; hh++) {
                float lo, hi; unpack2(acc[j][hh], lo, hi);
                v[hh] = fmaxf(lo + hi + bb[hh], 0.0f);
            }
            float4* dst = (float4*)&sm[U_H1S + a * 68 + warp * 8];
            dst[0] = make_float4(v[0], v[1], v[2], v[3]);
            dst[1] = make_float4(v[4], v[5], v[6], v[7]);
        }
    }
    __syncthreads();

    // ---- layers 2+3 fused: thread tid handles atom slot tid ----
    {
        float h1r[H1_];
        #pragma unroll
        for (int q = 0; q < 16; q++)
            *(float4*)&h1r[q * 4] = *(const float4*)&sm[U_H1S + tid * 68 + q * 4];

        unsigned long long accg[8];
        #pragma unroll
        for (int gp = 0; gp < 8; gp++)
            accg[gp] = *(const unsigned long long*)&sm[S_B2 + gp * 2];

        const unsigned long long* w2q = (const unsigned long long*)&sm[S_W2];
        #pragma unroll 8
        for (int k = 0; k < H1_; k++) {
            unsigned long long hkk = pack2(h1r[k], h1r[k]);
            #pragma unroll
            for (int gp = 0; gp < 8; gp++)
                ffma2(accg[gp], hkk, w2q[k * 8 + gp]);
        }

        float o = sm[S_MISC + 1];              // b3[t]
        #pragma unroll
        for (int gp = 0; gp < 8; gp++) {
            float lo, hi; unpack2(accg[gp], lo, hi);
            o += fmaxf(lo, 0.0f) * sm[S_W3 + gp * 2]
               + fmaxf(hi, 0.0f) * sm[S_W3 + gp * 2 + 1];
        }
        if (idx >= 0)
            g_atom[idx] = (o + sm[S_MISC]) * mask[idx];
    }
}

// ===========================================================================
// K3: deterministic reduction — warp per molecule, fixed shuffle tree.
// ===========================================================================
__global__ void k_reduce(float* __restrict__ out) {
    int warp = threadIdx.x >> 5, lane = threadIdx.x & 31;
    int m = blockIdx.x * 8 + warp;
    const float* p = g_atom + m * A_;
    float s = p[lane] + p[lane + 32];
    #pragma unroll
    for (int o = 16; o > 0; o >>= 1) s += __shfl_xor_sync(0xffffffffu, s, o);
    if (lane == 0) out[m] = s;
}

// ===========================================================================
extern "C" void kernel_launch(void* const* d_in, const int* in_sizes, int n_in,
                              void* d_out, int out_size) {
    const float* x    = (const float*)d_in[0];
    const float* mask = (const float*)d_in[1];
    const float* W1   = (const float*)d_in[2];
    const float* b1   = (const float*)d_in[3];
    const float* W2   = (const float*)d_in[4];
    const float* b2   = (const float*)d_in[5];
    const float* W3   = (const float*)d_in[6];
    const float* b3   = (const float*)d_in[7];

    cudaFuncSetAttribute(k_mlp, cudaFuncAttributeMaxDynamicSharedMemorySize,
                         SMEM_BYTES);

    k_init<<<1, 32>>>(b1, W2, b2, W3, b3);
    k_bucket<<<NATOM / 256, 256>>>(x);
    k_mlp<<<MLP_BLOCKS, 256, SMEM_BYTES>>>(x, mask, W1, b1, W2, b2, W3, b3);
    k_reduce<<<B_ / 8, 256>>>((float*)d_out);
}

// round 5
// speedup vs baseline: 1.8221x; 1.8221x over previous
#include <cuda_runtime.h>
#include <cstdint>

// ---------------------------------------------------------------------------
// MultiMolNet: per-atom typed 3-layer MLP + masked per-molecule sum.
// Identity: sum over all 8 type-MLPs = f_{type}(feats) + (C - Z_type),
// Z_t = f_t(0), C = sum_t Z_t  ->  one MLP eval per atom (8x fewer FLOPs).
//
// R5: coalesced warp-cooperative feature loads + cp.async double-buffered
//     pipeline (loads overlap FFMA), LDS.128 for W2 in layer 2.
// ---------------------------------------------------------------------------

namespace {
constexpr int B_  = 4096;
constexpr int A_  = 64;
constexpr int F_  = 124;
constexpr int T_  = 8;
constexpr int H1_ = 64;
constexpr int H2_ = 16;
constexpr int NATOM = B_ * A_;     // 262144
constexpr int ROW   = F_ + 1;      // 125
constexpr int BM    = 256;         // atoms per MLP tile
constexpr int MLP_BLOCKS = NATOM / BM + T_;   // >= sum of ceil(cnt_t/BM)

// --- dynamic smem layout (float indices) ---
// W1T [64][126] then two feature chunk buffers fa0/fa1 [256][34].
// Layer-2 view h1s[256][68] overlays [0..17408) -- only live after all
// layer-1 reads are done (barrier-protected).
constexpr int U_W1T = 0;               // 8064
constexpr int U_FA0 = 8064;            // 8704
constexpr int U_FA1 = 16768;           // 8704
constexpr int U_H1S = 0;               // 17408 (overlay)
constexpr int S_W2  = 25472;           // 1024 (16B aligned: 25472*4 % 16 == 0)
constexpr int S_B1  = S_W2 + 1024;     // 64
constexpr int S_B2  = S_B1 + 64;       // 16
constexpr int S_W3  = S_B2 + 16;       // 16
constexpr int S_MISC = S_W3 + 16;      // [0]=corr, [1]=b3[t]
constexpr int SMEM_FLOATS = S_MISC + 4;
constexpr int SMEM_BYTES  = SMEM_FLOATS * 4;   // ~104 KB
}

// ---- scratch (no allocations allowed) ----
__device__ int   g_counts[T_];
__device__ int   g_bucket[T_ * NATOM];      // 8 MB
__device__ float g_corr[T_];                // C - Z_t
__device__ float g_atom[NATOM];             // per-atom masked contribution

// ---- f32x2 packed FMA (PTX-only on sm_103a) ----
__device__ __forceinline__ void ffma2(unsigned long long& d,
                                      unsigned long long a,
                                      unsigned long long b) {
    asm("fma.rn.f32x2 %0, %1, %2, %3;" : "=l"(d) : "l"(a), "l"(b), "l"(d));
}
__device__ __forceinline__ unsigned long long pack2(float lo, float hi) {
    unsigned long long r;
    asm("mov.b64 %0, {%1, %2};" : "=l"(r) : "f"(lo), "f"(hi));
    return r;
}
__device__ __forceinline__ void unpack2(unsigned long long v, float& lo, float& hi) {
    asm("mov.b64 {%0, %1}, %2;" : "=f"(lo), "=f"(hi) : "l"(v));
}

// ---- cp.async helpers ----
__device__ __forceinline__ void cp_async4(uint32_t dst, const void* src) {
    asm volatile("cp.async.ca.shared.global [%0], [%1], 4;"
                 :: "r"(dst), "l"(src) : "memory");
}
#define CP_COMMIT() asm volatile("cp.async.commit_group;" ::: "memory")
#define CP_WAIT(n)  asm volatile("cp.async.wait_group %0;" :: "n"(n) : "memory")

// ===========================================================================
// K0: compute Z_t = f_t(0), corr_t = C - Z_t; zero type counters.
// ===========================================================================
__global__ void k_init(const float* __restrict__ b1, const float* __restrict__ W2,
                       const float* __restrict__ b2, const float* __restrict__ W3,
                       const float* __restrict__ b3) {
    __shared__ float zs[T_];
    int t = threadIdx.x;
    if (t < T_) {
        g_counts[t] = 0;
        float h1z[H1_];
        #pragma unroll
        for (int h = 0; h < H1_; h++) h1z[h] = fmaxf(b1[t * H1_ + h], 0.0f);
        float o = b3[t];
        for (int g = 0; g < H2_; g++) {
            float s = b2[t * H2_ + g];
            #pragma unroll
            for (int k = 0; k < H1_; k++)
                s += h1z[k] * W2[t * H1_ * H2_ + k * H2_ + g];
            o += fmaxf(s, 0.0f) * W3[t * H2_ + g];
        }
        zs[t] = o;
    }
    __syncthreads();
    if (t < T_) {
        float C = 0.0f;
        #pragma unroll
        for (int tt = 0; tt < T_; tt++) C += zs[tt];
        g_corr[t] = C - zs[t];
    }
}

// ===========================================================================
// K1: bucket atom indices by type (block-aggregated atomics). Bucket order
// is nondeterministic but harmless: per-atom values and the reduction tree
// are independent of bucket position.
// ===========================================================================
__global__ void k_bucket(const float* __restrict__ x) {
    __shared__ int scnt[T_], sbase[T_];
    int tid = threadIdx.x;
    if (tid < T_) scnt[tid] = 0;
    __syncthreads();
    int i = blockIdx.x * 256 + tid;
    int t = (int)x[(long long)i * ROW];
    int r = atomicAdd(&scnt[t], 1);
    __syncthreads();
    if (tid < T_) sbase[tid] = atomicAdd(&g_counts[tid], scnt[tid]);
    __syncthreads();
    g_bucket[t * NATOM + sbase[t] + r] = i;
}

// ===========================================================================
// K2: fused 3-layer MLP per (type, 256-atom tile).
// ===========================================================================

// Issue one 32-wide feature chunk for this warp's 32 atom slots via cp.async.
// Lane l loads feature (kb + l) of atom slot (warp*32 + a); atom index is
// shuffled from the thread that owns that slot. Invalid slots / lanes >= kl
// skip (stale smem never read: compute uses only np = kl/2 pairs).
__device__ __forceinline__ void issue_chunk(const float* __restrict__ x,
                                            uint32_t fa_u32, int warp, int lane,
                                            int my_idx, int kb, int kl) {
    const int slot0 = warp * 32;
    #pragma unroll 8
    for (int a = 0; a < 32; a++) {
        int sid = __shfl_sync(0xffffffffu, my_idx, a);
        if (sid >= 0 && lane < kl) {
            const float* src = x + (long long)sid * ROW + 1 + kb + lane;
            cp_async4(fa_u32 + (uint32_t)((slot0 + a) * 34 + lane) * 4u, src);
        }
    }
}

// One K-chunk of layer 1: 8 atoms x 8 h per thread, f32x2 over (k,k+1) pairs.
__device__ __forceinline__ void compute_chunk(const float* __restrict__ sm,
                                              const float* __restrict__ fabuf,
                                              int warp, int lane, int kb, int np,
                                              unsigned long long acc[8][8]) {
    const unsigned long long* wq =
        (const unsigned long long*)&sm[U_W1T + warp * 8 * 126 + kb];
    const unsigned long long* fq =
        (const unsigned long long*)&fabuf[lane * 34];
    #pragma unroll 1
    for (int kp = 0; kp < np; kp++) {
        unsigned long long wp[8], fp[8];
        #pragma unroll
        for (int hh = 0; hh < 8; hh++) wp[hh] = wq[hh * 63];   // bcast, row 126 fl
        #pragma unroll
        for (int j = 0; j < 8; j++)    fp[j]  = fq[j * 544];   // 32 atoms * 34 fl
        #pragma unroll
        for (int j = 0; j < 8; j++)
            #pragma unroll
            for (int hh = 0; hh < 8; hh++)
                ffma2(acc[j][hh], fp[j], wp[hh]);
        wq++; fq++;
    }
}

__global__ void __launch_bounds__(256, 1)
k_mlp(const float* __restrict__ x,  const float* __restrict__ mask,
      const float* __restrict__ W1, const float* __restrict__ b1,
      const float* __restrict__ W2, const float* __restrict__ b2,
      const float* __restrict__ W3, const float* __restrict__ b3) {
    extern __shared__ float sm[];
    const int tid  = threadIdx.x;
    const int warp = tid >> 5;
    const int lane = tid & 31;

    // ---- map block -> (type, tile) ----
    int t = -1, tile = 0, cnt = 0;
    {
        int rem = blockIdx.x;
        #pragma unroll
        for (int tt = 0; tt < T_; tt++) {
            int c  = g_counts[tt];
            int nt = (c + BM - 1) >> 8;
            if (t < 0) {
                if (rem < nt) { t = tt; tile = rem; cnt = c; }
                else rem -= nt;
            }
        }
    }
    if (t < 0) return;   // uniform exit, before any sync

    // ---- small param staging (normal LDG/STS) ----
    for (int i = tid; i < H1_ * H2_; i += 256)
        sm[S_W2 + i] = W2[t * H1_ * H2_ + i];
    if (tid < H1_) sm[S_B1 + tid] = b1[t * H1_ + tid];
    if (tid < H2_) sm[S_B2 + tid] = b2[t * H2_ + tid];
    if (tid < H2_) sm[S_W3 + tid] = W3[t * H2_ + tid];
    if (tid == 0) { sm[S_MISC] = g_corr[t]; sm[S_MISC + 1] = b3[t]; }

    // this thread's atom slot (slot tid)
    const int gi  = tile * BM + tid;
    const int idx = (gi < cnt) ? g_bucket[t * NATOM + gi] : -1;

    // ---- W1 -> transposed smem via cp.async (group 0 with chunk 0) ----
    const uint32_t sm_u32  = (uint32_t)__cvta_generic_to_shared(sm);
    const uint32_t fa0_u32 = sm_u32 + U_FA0 * 4;
    const uint32_t fa1_u32 = sm_u32 + U_FA1 * 4;
    {
        const float* w1t_src = W1 + t * F_ * H1_;
        #pragma unroll
        for (int k = 0; k < 31; k++) {
            int i = tid + k * 256;            // 31*256 = 7936 exactly
            int h = i & 63, f = i >> 6;
            cp_async4(sm_u32 + (uint32_t)(U_W1T + h * 126 + f) * 4u, w1t_src + i);
        }
    }

    unsigned long long acc[8][8];
    #pragma unroll
    for (int j = 0; j < 8; j++)
        #pragma unroll
        for (int hh = 0; hh < 8; hh++) acc[j][hh] = 0ULL;

    // ---- double-buffered cp.async pipeline over 4 K-chunks {32,32,32,28} ----
    issue_chunk(x, fa0_u32, warp, lane, idx, 0, 32);  CP_COMMIT();  // g0: W1+c0
    issue_chunk(x, fa1_u32, warp, lane, idx, 32, 32); CP_COMMIT();  // g1: c1
    CP_WAIT(1); __syncthreads();                       // g0 resident
    compute_chunk(sm, &sm[U_FA0], warp, lane, 0, 16, acc);
    __syncthreads();                                   // fa0 free
    issue_chunk(x, fa0_u32, warp, lane, idx, 64, 32); CP_COMMIT();  // g2: c2
    CP_WAIT(1); __syncthreads();                       // g1 resident
    compute_chunk(sm, &sm[U_FA1], warp, lane, 32, 16, acc);
    __syncthreads();                                   // fa1 free
    issue_chunk(x, fa1_u32, warp, lane, idx, 96, 28); CP_COMMIT();  // g3: c3
    CP_WAIT(0); __syncthreads();                       // g2+g3 resident
    compute_chunk(sm, &sm[U_FA0], warp, lane, 64, 16, acc);
    compute_chunk(sm, &sm[U_FA1], warp, lane, 96, 14, acc);
    __syncthreads();                                   // all layer-1 reads done

    // ---- layer-1 epilogue: relu(lo+hi+b1) -> h1s[atom][h] (overlays U) ----
    {
        float bb[8];
        #pragma unroll
        for (int hh = 0; hh < 8; hh++) bb[hh] = sm[S_B1 + warp * 8 + hh];
        #pragma unroll
        for (int j = 0; j < 8; j++) {
            const int a = j * 32 + lane;
            float v[8];
            #pragma unroll
            for (int hh = 0; hh < 8; hh++) {
                float lo, hi; unpack2(acc[j][hh], lo, hi);
                v[hh] = fmaxf(lo + hi + bb[hh], 0.0f);
            }
            float4* dst = (float4*)&sm[U_H1S + a * 68 + warp * 8];
            dst[0] = make_float4(v[0], v[1], v[2], v[3]);
            dst[1] = make_float4(v[4], v[5], v[6], v[7]);
        }
    }
    __syncthreads();

    // ---- layers 2+3 fused: thread tid handles atom slot tid ----
    {
        float h1r[H1_];
        #pragma unroll
        for (int q = 0; q < 16; q++)
            *(float4*)&h1r[q * 4] = *(const float4*)&sm[U_H1S + tid * 68 + q * 4];

        unsigned long long accg[8];
        #pragma unroll
        for (int gp = 0; gp < 8; gp++)
            accg[gp] = *(const unsigned long long*)&sm[S_B2 + gp * 2];

        const ulonglong2* w2v = (const ulonglong2*)&sm[S_W2];  // 16B aligned
        #pragma unroll 8
        for (int k = 0; k < H1_; k++) {
            unsigned long long hkk = pack2(h1r[k], h1r[k]);
            #pragma unroll
            for (int gq = 0; gq < 4; gq++) {
                ulonglong2 w = w2v[k * 4 + gq];
                ffma2(accg[gq * 2],     hkk, w.x);
                ffma2(accg[gq * 2 + 1], hkk, w.y);
            }
        }

        float o = sm[S_MISC + 1];              // b3[t]
        #pragma unroll
        for (int gp = 0; gp < 8; gp++) {
            float lo, hi; unpack2(accg[gp], lo, hi);
            o += fmaxf(lo, 0.0f) * sm[S_W3 + gp * 2]
               + fmaxf(hi, 0.0f) * sm[S_W3 + gp * 2 + 1];
        }
        if (idx >= 0)
            g_atom[idx] = (o + sm[S_MISC]) * mask[idx];
    }
}

// ===========================================================================
// K3: deterministic reduction — warp per molecule, fixed shuffle tree.
// ===========================================================================
__global__ void k_reduce(float* __restrict__ out) {
    int warp = threadIdx.x >> 5, lane = threadIdx.x & 31;
    int m = blockIdx.x * 8 + warp;
    const float* p = g_atom + m * A_;
    float s = p[lane] + p[lane + 32];
    #pragma unroll
    for (int o = 16; o > 0; o >>= 1) s += __shfl_xor_sync(0xffffffffu, s, o);
    if (lane == 0) out[m] = s;
}

// ===========================================================================
extern "C" void kernel_launch(void* const* d_in, const int* in_sizes, int n_in,
                              void* d_out, int out_size) {
    const float* x    = (const float*)d_in[0];
    const float* mask = (const float*)d_in[1];
    const float* W1   = (const float*)d_in[2];
    const float* b1   = (const float*)d_in[3];
    const float* W2   = (const float*)d_in[4];
    const float* b2   = (const float*)d_in[5];
    const float* W3   = (const float*)d_in[6];
    const float* b3   = (const float*)d_in[7];

    cudaFuncSetAttribute(k_mlp, cudaFuncAttributeMaxDynamicSharedMemorySize,
                         SMEM_BYTES);

    k_init<<<1, 32>>>(b1, W2, b2, W3, b3);
    k_bucket<<<NATOM / 256, 256>>>(x);
    k_mlp<<<MLP_BLOCKS, 256, SMEM_BYTES>>>(x, mask, W1, b1, W2, b2, W3, b3);
    k_reduce<<<B_ / 8, 256>>>((float*)d_out);
}

// round 6
// speedup vs baseline: 1.8352x; 1.0072x over previous
#include <cuda_runtime.h>
#include <cstdint>

// ---------------------------------------------------------------------------
// MultiMolNet: per-atom typed 3-layer MLP + masked per-molecule sum.
// Identity: sum over all 8 type-MLPs = f_{type}(feats) + (C - Z_type),
// Z_t = f_t(0), C = sum_t Z_t  ->  one MLP eval per atom (8x fewer FLOPs).
//
// R6: 2 CTAs/SM (BM=128, 64-reg accumulator tile, 72KB smem) for cross-CTA
//     overlap of load phases and barriers; smem-staged atom indices.
// ---------------------------------------------------------------------------

namespace {
constexpr int B_  = 4096;
constexpr int A_  = 64;
constexpr int F_  = 124;
constexpr int T_  = 8;
constexpr int H1_ = 64;
constexpr int H2_ = 16;
constexpr int NATOM = B_ * A_;     // 262144
constexpr int ROW   = F_ + 1;      // 125
constexpr int BM    = 128;         // atoms per MLP tile
constexpr int MLP_BLOCKS = NATOM / BM + T_;   // 2056 >= sum ceil(cnt_t/BM)

// --- dynamic smem layout (float indices) ---
// W1T [64][126], two feature buffers fa0/fa1 [128][34].
// Layer-2 view h1s[128][68] overlays [0..8704) (barrier-protected).
constexpr int U_W1T = 0;               // 8064
constexpr int U_FA0 = 8064;            // 4352
constexpr int U_FA1 = 12416;           // 4352
constexpr int U_H1S = 0;               // 8704 (overlay)
constexpr int S_W2  = 16768;           // 1024 (16B aligned)
constexpr int S_B1  = S_W2 + 1024;     // 64
constexpr int S_B2  = S_B1 + 64;       // 16
constexpr int S_W3  = S_B2 + 16;       // 16
constexpr int S_MISC = S_W3 + 16;      // [0]=corr, [1]=b3[t]
constexpr int S_IDX  = S_MISC + 4;     // 128 ints (atom index per slot)
constexpr int SMEM_FLOATS = S_IDX + BM;
constexpr int SMEM_BYTES  = SMEM_FLOATS * 4;   // ~72 KB -> 2 CTAs/SM
}

// ---- scratch (no allocations allowed) ----
__device__ int   g_counts[T_];
__device__ int   g_bucket[T_ * NATOM];      // 8 MB
__device__ float g_corr[T_];                // C - Z_t
__device__ float g_atom[NATOM];             // per-atom masked contribution

// ---- f32x2 packed FMA (PTX-only on sm_103a) ----
__device__ __forceinline__ void ffma2(unsigned long long& d,
                                      unsigned long long a,
                                      unsigned long long b) {
    asm("fma.rn.f32x2 %0, %1, %2, %3;" : "=l"(d) : "l"(a), "l"(b), "l"(d));
}
__device__ __forceinline__ unsigned long long pack2(float lo, float hi) {
    unsigned long long r;
    asm("mov.b64 %0, {%1, %2};" : "=l"(r) : "f"(lo), "f"(hi));
    return r;
}
__device__ __forceinline__ void unpack2(unsigned long long v, float& lo, float& hi) {
    asm("mov.b64 {%0, %1}, %2;" : "=f"(lo), "=f"(hi) : "l"(v));
}

// ---- cp.async helpers ----
__device__ __forceinline__ void cp_async4(uint32_t dst, const void* src) {
    asm volatile("cp.async.ca.shared.global [%0], [%1], 4;"
                 :: "r"(dst), "l"(src) : "memory");
}
#define CP_COMMIT() asm volatile("cp.async.commit_group;" ::: "memory")
#define CP_WAIT(n)  asm volatile("cp.async.wait_group %0;" :: "n"(n) : "memory")

// ===========================================================================
// K0: compute Z_t = f_t(0), corr_t = C - Z_t; zero type counters.
// ===========================================================================
__global__ void k_init(const float* __restrict__ b1, const float* __restrict__ W2,
                       const float* __restrict__ b2, const float* __restrict__ W3,
                       const float* __restrict__ b3) {
    __shared__ float zs[T_];
    int t = threadIdx.x;
    if (t < T_) {
        g_counts[t] = 0;
        float h1z[H1_];
        #pragma unroll
        for (int h = 0; h < H1_; h++) h1z[h] = fmaxf(b1[t * H1_ + h], 0.0f);
        float o = b3[t];
        for (int g = 0; g < H2_; g++) {
            float s = b2[t * H2_ + g];
            #pragma unroll
            for (int k = 0; k < H1_; k++)
                s += h1z[k] * W2[t * H1_ * H2_ + k * H2_ + g];
            o += fmaxf(s, 0.0f) * W3[t * H2_ + g];
        }
        zs[t] = o;
    }
    __syncthreads();
    if (t < T_) {
        float C = 0.0f;
        #pragma unroll
        for (int tt = 0; tt < T_; tt++) C += zs[tt];
        g_corr[t] = C - zs[t];
    }
}

// ===========================================================================
// K1: bucket atom indices by type (block-aggregated atomics). Bucket order
// is nondeterministic but harmless: per-atom values and the reduction tree
// are independent of bucket position.
// ===========================================================================
__global__ void k_bucket(const float* __restrict__ x) {
    __shared__ int scnt[T_], sbase[T_];
    int tid = threadIdx.x;
    if (tid < T_) scnt[tid] = 0;
    __syncthreads();
    int i = blockIdx.x * 256 + tid;
    int t = (int)x[(long long)i * ROW];
    int r = atomicAdd(&scnt[t], 1);
    __syncthreads();
    if (tid < T_) sbase[tid] = atomicAdd(&g_counts[tid], scnt[tid]);
    __syncthreads();
    g_bucket[t * NATOM + sbase[t] + r] = i;
}

// ===========================================================================
// K2: fused 3-layer MLP per (type, 128-atom tile), 2 CTAs/SM.
//   layer 1: warp w owns h in [8w,8w+8); lane owns atoms {lane+32j}, j<4
//   f32x2 accumulators over (k,k+1) pairs; all operands via LDS.64.
// ===========================================================================

// Warp-cooperative cp.async of one 32-wide feature chunk. Warp w fills atom
// slots [16w, 16w+16); lane = feature within chunk. Atom index comes from
// smem (LDS broadcast). Stale smem for short/invalid slots is never read.
__device__ __forceinline__ void issue_chunk(const float* __restrict__ x,
                                            const int* __restrict__ s_idx,
                                            uint32_t fa_u32, int warp, int lane,
                                            int kb, int kl) {
    const int slot0 = warp * 16;
    #pragma unroll
    for (int a = 0; a < 16; a++) {
        int sid = s_idx[slot0 + a];
        if (sid >= 0 && lane < kl) {
            const float* src = x + (long long)sid * ROW + 1 + kb + lane;
            cp_async4(fa_u32 + (uint32_t)((slot0 + a) * 34 + lane) * 4u, src);
        }
    }
}

// One K-chunk of layer 1: 4 atoms x 8 h per thread.
__device__ __forceinline__ void compute_chunk(const float* __restrict__ sm,
                                              const float* __restrict__ fabuf,
                                              int warp, int lane, int kb, int np,
                                              unsigned long long acc[4][8]) {
    const unsigned long long* wq =
        (const unsigned long long*)&sm[U_W1T + warp * 8 * 126 + kb];
    const unsigned long long* fq =
        (const unsigned long long*)&fabuf[lane * 34];
    #pragma unroll 1
    for (int kp = 0; kp < np; kp++) {
        unsigned long long wp[8], fp[4];
        #pragma unroll
        for (int hh = 0; hh < 8; hh++) wp[hh] = wq[hh * 63];   // bcast, row 126 fl
        #pragma unroll
        for (int j = 0; j < 4; j++)    fp[j]  = fq[j * 544];   // 32 atoms * 34 fl
        #pragma unroll
        for (int j = 0; j < 4; j++)
            #pragma unroll
            for (int hh = 0; hh < 8; hh++)
                ffma2(acc[j][hh], fp[j], wp[hh]);
        wq++; fq++;
    }
}

__global__ void __launch_bounds__(256, 2)
k_mlp(const float* __restrict__ x,  const float* __restrict__ mask,
      const float* __restrict__ W1, const float* __restrict__ b1,
      const float* __restrict__ W2, const float* __restrict__ b2,
      const float* __restrict__ W3, const float* __restrict__ b3) {
    extern __shared__ float sm[];
    int* s_idx = (int*)&sm[S_IDX];
    const int tid  = threadIdx.x;
    const int warp = tid >> 5;
    const int lane = tid & 31;

    // ---- map block -> (type, tile) ----
    int t = -1, tile = 0, cnt = 0;
    {
        int rem = blockIdx.x;
        #pragma unroll
        for (int tt = 0; tt < T_; tt++) {
            int c  = g_counts[tt];
            int nt = (c + BM - 1) >> 7;
            if (t < 0) {
                if (rem < nt) { t = tt; tile = rem; cnt = c; }
                else rem -= nt;
            }
        }
    }
    if (t < 0) return;   // uniform exit, before any sync

    // ---- small param staging ----
    for (int i = tid; i < H1_ * H2_; i += 256)
        sm[S_W2 + i] = W2[t * H1_ * H2_ + i];
    if (tid < H1_) sm[S_B1 + tid] = b1[t * H1_ + tid];
    if (tid < H2_) sm[S_B2 + tid] = b2[t * H2_ + tid];
    if (tid < H2_) sm[S_W3 + tid] = W3[t * H2_ + tid];
    if (tid == 0) { sm[S_MISC] = g_corr[t]; sm[S_MISC + 1] = b3[t]; }

    // ---- atom indices for this tile -> smem ----
    if (tid < BM) {
        int gi = tile * BM + tid;
        s_idx[tid] = (gi < cnt) ? g_bucket[t * NATOM + gi] : -1;
    }

    // ---- W1 -> transposed smem via cp.async (group 0 with chunk 0) ----
    const uint32_t sm_u32  = (uint32_t)__cvta_generic_to_shared(sm);
    const uint32_t fa0_u32 = sm_u32 + U_FA0 * 4;
    const uint32_t fa1_u32 = sm_u32 + U_FA1 * 4;
    {
        const float* w1t_src = W1 + t * F_ * H1_;
        #pragma unroll
        for (int k = 0; k < 31; k++) {
            int i = tid + k * 256;            // 31*256 = 7936 exactly
            int h = i & 63, f = i >> 6;
            cp_async4(sm_u32 + (uint32_t)(U_W1T + h * 126 + f) * 4u, w1t_src + i);
        }
    }
    __syncthreads();                          // s_idx visible to all warps

    unsigned long long acc[4][8];
    #pragma unroll
    for (int j = 0; j < 4; j++)
        #pragma unroll
        for (int hh = 0; hh < 8; hh++) acc[j][hh] = 0ULL;

    // ---- double-buffered cp.async pipeline over 4 K-chunks {32,32,32,28} ----
    issue_chunk(x, s_idx, fa0_u32, warp, lane, 0, 32);  CP_COMMIT();  // g0: W1+c0
    issue_chunk(x, s_idx, fa1_u32, warp, lane, 32, 32); CP_COMMIT();  // g1: c1
    CP_WAIT(1); __syncthreads();                        // g0 resident
    compute_chunk(sm, &sm[U_FA0], warp, lane, 0, 16, acc);
    __syncthreads();                                    // fa0 free
    issue_chunk(x, s_idx, fa0_u32, warp, lane, 64, 32); CP_COMMIT();  // g2: c2
    CP_WAIT(1); __syncthreads();                        // g1 resident
    compute_chunk(sm, &sm[U_FA1], warp, lane, 32, 16, acc);
    __syncthreads();                                    // fa1 free
    issue_chunk(x, s_idx, fa1_u32, warp, lane, 96, 28); CP_COMMIT();  // g3: c3
    CP_WAIT(0); __syncthreads();                        // g2+g3 resident
    compute_chunk(sm, &sm[U_FA0], warp, lane, 64, 16, acc);
    compute_chunk(sm, &sm[U_FA1], warp, lane, 96, 14, acc);
    __syncthreads();                                    // all layer-1 reads done

    // ---- layer-1 epilogue: relu(lo+hi+b1) -> h1s[atom][h] (overlays U) ----
    {
        float bb[8];
        #pragma unroll
        for (int hh = 0; hh < 8; hh++) bb[hh] = sm[S_B1 + warp * 8 + hh];
        #pragma unroll
        for (int j = 0; j < 4; j++) {
            const int a = j * 32 + lane;
            float v[8];
            #pragma unroll
            for (int hh = 0; hh < 8; hh++) {
                float lo, hi; unpack2(acc[j][hh], lo, hi);
                v[hh] = fmaxf(lo + hi + bb[hh], 0.0f);
            }
            float4* dst = (float4*)&sm[U_H1S + a * 68 + warp * 8];
            dst[0] = make_float4(v[0], v[1], v[2], v[3]);
            dst[1] = make_float4(v[4], v[5], v[6], v[7]);
        }
    }
    __syncthreads();

    // ---- layers 2+3 fused: threads 0..127 handle atom slot tid ----
    if (tid < BM) {
        float h1r[H1_];
        #pragma unroll
        for (int q = 0; q < 16; q++)
            *(float4*)&h1r[q * 4] = *(const float4*)&sm[U_H1S + tid * 68 + q * 4];

        unsigned long long accg[8];
        #pragma unroll
        for (int gp = 0; gp < 8; gp++)
            accg[gp] = *(const unsigned long long*)&sm[S_B2 + gp * 2];

        const ulonglong2* w2v = (const ulonglong2*)&sm[S_W2];  // 16B aligned
        #pragma unroll 8
        for (int k = 0; k < H1_; k++) {
            unsigned long long hkk = pack2(h1r[k], h1r[k]);
            #pragma unroll
            for (int gq = 0; gq < 4; gq++) {
                ulonglong2 w = w2v[k * 4 + gq];
                ffma2(accg[gq * 2],     hkk, w.x);
                ffma2(accg[gq * 2 + 1], hkk, w.y);
            }
        }

        float o = sm[S_MISC + 1];              // b3[t]
        #pragma unroll
        for (int gp = 0; gp < 8; gp++) {
            float lo, hi; unpack2(accg[gp], lo, hi);
            o += fmaxf(lo, 0.0f) * sm[S_W3 + gp * 2]
               + fmaxf(hi, 0.0f) * sm[S_W3 + gp * 2 + 1];
        }
        int idx = s_idx[tid];
        if (idx >= 0)
            g_atom[idx] = (o + sm[S_MISC]) * mask[idx];
    }
}

// ===========================================================================
// K3: deterministic reduction — warp per molecule, fixed shuffle tree.
// ===========================================================================
__global__ void k_reduce(float* __restrict__ out) {
    int warp = threadIdx.x >> 5, lane = threadIdx.x & 31;
    int m = blockIdx.x * 8 + warp;
    const float* p = g_atom + m * A_;
    float s = p[lane] + p[lane + 32];
    #pragma unroll
    for (int o = 16; o > 0; o >>= 1) s += __shfl_xor_sync(0xffffffffu, s, o);
    if (lane == 0) out[m] = s;
}

// ===========================================================================
extern "C" void kernel_launch(void* const* d_in, const int* in_sizes, int n_in,
                              void* d_out, int out_size) {
    const float* x    = (const float*)d_in[0];
    const float* mask = (const float*)d_in[1];
    const float* W1   = (const float*)d_in[2];
    const float* b1   = (const float*)d_in[3];
    const float* W2   = (const float*)d_in[4];
    const float* b2   = (const float*)d_in[5];
    const float* W3   = (const float*)d_in[6];
    const float* b3   = (const float*)d_in[7];

    cudaFuncSetAttribute(k_mlp, cudaFuncAttributeMaxDynamicSharedMemorySize,
                         SMEM_BYTES);

    k_init<<<1, 32>>>(b1, W2, b2, W3, b3);
    k_bucket<<<NATOM / 256, 256>>>(x);
    k_mlp<<<MLP_BLOCKS, 256, SMEM_BYTES>>>(x, mask, W1, b1, W2, b2, W3, b3);
    k_reduce<<<B_ / 8, 256>>>((float*)d_out);
}